// round 15
// baseline (speedup 1.0000x reference)
#include <cuda_runtime.h>
#include <cuda_bf16.h>
#include <cstdint>
#include <math.h>

// Problem dims (fixed)
#define B_SZ   4096
#define N_IN   4096
#define N_CTX  512
#define UNITS  4096
#define RANK   256

// ---------------------------------------------------------------------------
// Device scratch
// ---------------------------------------------------------------------------
__device__ __align__(16) unsigned short g_ctx_hi[B_SZ * N_CTX];
__device__ __align__(16) unsigned short g_ctx_lo[B_SZ * N_CTX];
__device__ __align__(16) unsigned short g_t_hi[B_SZ * RANK];
__device__ __align__(16) unsigned short g_t_lo[B_SZ * RANK];
__device__ __align__(16) unsigned short g_Ut_hi[RANK * N_IN];   // U^T [256][4096]
__device__ __align__(16) unsigned short g_Ut_lo[RANK * N_IN];
__device__ __align__(16) unsigned short g_V_hi[UNITS * RANK];
__device__ __align__(16) unsigned short g_V_lo[UNITS * RANK];
__device__ __align__(16) unsigned short g_Wt_hi[RANK * N_CTX];  // W^T [256][512]
__device__ __align__(16) unsigned short g_Wt_lo[RANK * N_CTX];
__device__ __align__(16) float          g_schi[B_SZ * RANK];
__device__ __align__(16) float          g_part[2][B_SZ * RANK];

// ---------------------------------------------------------------------------
// Helpers
// ---------------------------------------------------------------------------
__device__ __forceinline__ uint32_t smem_to_u32(const void* p) {
    uint32_t a;
    asm("{ .reg .u64 t; cvta.to.shared.u64 t, %1; cvt.u32.u64 %0, t; }"
        : "=r"(a) : "l"(p));
    return a;
}

__device__ __forceinline__ void ldmx4(uint32_t* r, uint32_t addr) {
    asm volatile("ldmatrix.sync.aligned.m8n8.x4.shared.b16 {%0,%1,%2,%3}, [%4];\n"
                 : "=r"(r[0]), "=r"(r[1]), "=r"(r[2]), "=r"(r[3]) : "r"(addr));
}

__device__ __forceinline__ void mma_bf16(float* c, const uint32_t* a, const uint32_t* b) {
    asm volatile(
        "mma.sync.aligned.m16n8k16.row.col.f32.bf16.bf16.f32 "
        "{%0,%1,%2,%3}, {%4,%5,%6,%7}, {%8,%9}, {%0,%1,%2,%3};\n"
        : "+f"(c[0]), "+f"(c[1]), "+f"(c[2]), "+f"(c[3])
        : "r"(a[0]), "r"(a[1]), "r"(a[2]), "r"(a[3]), "r"(b[0]), "r"(b[1]));
}

#define CP_ASYNC16(saddr, gptr) \
    asm volatile("cp.async.cg.shared.global [%0], [%1], 16;\n" \
                 :: "r"(saddr), "l"(gptr))
#define CP_COMMIT() asm volatile("cp.async.commit_group;\n" ::: "memory")

template <int N>
__device__ __forceinline__ void cp_wait_group() {
    asm volatile("cp.async.wait_group %0;\n" :: "n"(N) : "memory");
}

__device__ __forceinline__ void split2(float x, unsigned short& h, unsigned short& l) {
    __nv_bfloat16 hb = __float2bfloat16_rn(x);
    h = *reinterpret_cast<unsigned short*>(&hb);
    float r = x - __bfloat162float(hb);
    __nv_bfloat16 lb = __float2bfloat16_rn(r);
    l = *reinterpret_cast<unsigned short*>(&lb);
}

// ---------------------------------------------------------------------------
// Fused prep kernels
// ---------------------------------------------------------------------------
__global__ __launch_bounds__(256)
void prep1(const float* __restrict__ ctx, const float* __restrict__ W)
{
    __shared__ float tile[32][33];
    int b = blockIdx.x, tid = threadIdx.x;
    if (b < 2048) {
        size_t i = ((size_t)b * 256 + tid) * 4;
        float4 v = *(const float4*)(ctx + i);
        ushort4 h, l;
        split2(v.x, h.x, l.x); split2(v.y, h.y, l.y);
        split2(v.z, h.z, l.z); split2(v.w, h.w, l.w);
        *(ushort4*)(g_ctx_hi + i) = h;
        *(ushort4*)(g_ctx_lo + i) = l;
    } else {
        int bb = b - 2048;
        int c0 = (bb & 7) * 32;
        int r0 = (bb >> 3) * 32;
        int tx = tid & 31, ty = tid >> 5;
        for (int i = ty; i < 32; i += 8)
            tile[i][tx] = W[(size_t)(r0 + i) * RANK + c0 + tx];
        __syncthreads();
        for (int i = ty; i < 32; i += 8) {
            int c = c0 + i, r = r0 + tx;
            unsigned short h, l;
            split2(tile[tx][i], h, l);
            g_Wt_hi[(size_t)c * N_CTX + r] = h;
            g_Wt_lo[(size_t)c * N_CTX + r] = l;
        }
    }
}

__global__ __launch_bounds__(256)
void prep2(const float* __restrict__ V, const float* __restrict__ U)
{
    __shared__ float tile[32][33];
    int b = blockIdx.x, tid = threadIdx.x;
    if (b < 1024) {
        size_t i = ((size_t)b * 256 + tid) * 4;
        float4 v = *(const float4*)(V + i);
        ushort4 h, l;
        split2(v.x, h.x, l.x); split2(v.y, h.y, l.y);
        split2(v.z, h.z, l.z); split2(v.w, h.w, l.w);
        *(ushort4*)(g_V_hi + i) = h;
        *(ushort4*)(g_V_lo + i) = l;
    } else {
        int bb = b - 1024;
        int c0 = (bb & 7) * 32;
        int r0 = (bb >> 3) * 32;
        int tx = tid & 31, ty = tid >> 5;
        for (int i = ty; i < 32; i += 8)
            tile[i][tx] = U[(size_t)(r0 + i) * RANK + c0 + tx];
        __syncthreads();
        for (int i = ty; i < 32; i += 8) {
            int c = c0 + i, r = r0 + tx;
            unsigned short h, l;
            split2(tile[tx][i], h, l);
            g_Ut_hi[(size_t)c * N_IN + r] = h;
            g_Ut_lo[(size_t)c * N_IN + r] = l;
        }
    }
}

// ---------------------------------------------------------------------------
// Template GEMM (pre-split A). EPI 0 (chi) and 2 (out).
// ---------------------------------------------------------------------------
template <int TILEM, int TILEN, int WARPS_M, int WARPS_N, int KTOT, int EPI,
          int STAGES, int MINCTA>
__global__ __launch_bounds__(WARPS_M * WARPS_N * 32, MINCTA)
void mma_gemm(float* __restrict__ outp,
              const float* __restrict__ ev0,   // EPI0: S, EPI2: bias
              const float* __restrict__ ev1)   // EPI0: Bvec
{
    constexpr int THREADS = WARPS_M * WARPS_N * 32;
    constexpr int WM = TILEM / WARPS_M;
    constexpr int MI = WM / 16;
    constexpr int NI = 4;
    constexpr int AHB = TILEM * 40 * 2;
    constexpr int BHB = TILEN * 40 * 2;
    constexpr int STG = 2 * AHB + 2 * BHB;
    constexpr int NC  = KTOT / 32;
    constexpr int A_IT = TILEM * 4 / THREADS;
    constexpr int B_IT = TILEN * 4 / THREADS;
    static_assert(WARPS_N * 32 == TILEN, "tile mismatch");

    extern __shared__ char smem[];
    const uint32_t sb = smem_to_u32(smem);

    const int tid = threadIdx.x;
    const int wid = tid >> 5, lid = tid & 31;
    const int wm = wid / WARPS_N, wn = wid % WARPS_N;
    const int warp_row = wm * WM;
    const int warp_col = wn * 32;
    const int brow = blockIdx.y * TILEM;
    const int bn0  = blockIdx.x * TILEN;

    const unsigned short* Ahg = (EPI == 0) ? g_ctx_hi : g_t_hi;
    const unsigned short* Alg = (EPI == 0) ? g_ctx_lo : g_t_lo;
    const unsigned short* Bhg = (EPI == 0) ? g_Wt_hi : g_V_hi;
    const unsigned short* Blg = (EPI == 0) ? g_Wt_lo : g_V_lo;

    float acc[MI][NI][4];
#pragma unroll
    for (int mi = 0; mi < MI; mi++)
#pragma unroll
        for (int ni = 0; ni < NI; ni++)
#pragma unroll
            for (int q = 0; q < 4; q++) acc[mi][ni][q] = 0.f;

    const uint32_t a_lane = (uint32_t)(((lid & 15) * 40 + (lid >> 4) * 8) * 2);
    const uint32_t b_lane = (uint32_t)((((lid & 7) + ((lid >> 4) << 3)) * 40 +
                                        ((lid >> 3) & 1) * 8) * 2);

    auto load_stage = [&](int s, int k0) {
        const uint32_t st = sb + (uint32_t)(s * STG);
#pragma unroll
        for (int it = 0; it < A_IT; it++) {
            int flat = it * THREADS + tid;
            int row = flat >> 2, seg = flat & 3;
            uint32_t off = (uint32_t)(row * 80 + seg * 16);
            size_t gi = (size_t)(brow + row) * KTOT + k0 + seg * 8;
            CP_ASYNC16(st + off, Ahg + gi);
            CP_ASYNC16(st + AHB + off, Alg + gi);
        }
#pragma unroll
        for (int it = 0; it < B_IT; it++) {
            int flat = it * THREADS + tid;
            int row = flat >> 2, seg = flat & 3;
            uint32_t off = (uint32_t)(row * 80 + seg * 16);
            size_t gi = (size_t)(bn0 + row) * KTOT + k0 + seg * 8;
            CP_ASYNC16(st + 2 * AHB + off, Bhg + gi);
            CP_ASYNC16(st + 2 * AHB + BHB + off, Blg + gi);
        }
    };

#pragma unroll
    for (int s = 0; s < STAGES - 1; s++) {
        load_stage(s, s * 32);
        CP_COMMIT();
    }

    for (int ch = 0; ch < NC; ch++) {
        cp_wait_group<STAGES - 2>();
        __syncthreads();

        if (ch + STAGES - 1 < NC)
            load_stage((ch + STAGES - 1) % STAGES, (ch + STAGES - 1) * 32);
        CP_COMMIT();

        const uint32_t cb = sb + (uint32_t)((ch % STAGES) * STG);
        const uint32_t Ah = cb, Al = cb + AHB, Bh = cb + 2 * AHB, Bl = Bh + BHB;
#pragma unroll
        for (int ks = 0; ks < 2; ks++) {
            uint32_t afh[MI][4], afl[MI][4], bfh[2][4], bfl[2][4];
#pragma unroll
            for (int mi = 0; mi < MI; mi++) {
                uint32_t ao = a_lane + (uint32_t)((warp_row + mi * 16) * 80 + ks * 32);
                ldmx4(afh[mi], Ah + ao);
                ldmx4(afl[mi], Al + ao);
            }
#pragma unroll
            for (int j = 0; j < 2; j++) {
                uint32_t bo = b_lane + (uint32_t)((warp_col + j * 16) * 80 + ks * 32);
                ldmx4(bfh[j], Bh + bo);
                ldmx4(bfl[j], Bl + bo);
            }
#pragma unroll
            for (int mi = 0; mi < MI; mi++)
#pragma unroll
                for (int ni = 0; ni < NI; ni++)
                    mma_bf16(acc[mi][ni], afh[mi], &bfh[ni >> 1][(ni & 1) * 2]);
#pragma unroll
            for (int mi = 0; mi < MI; mi++)
#pragma unroll
                for (int ni = 0; ni < NI; ni++)
                    mma_bf16(acc[mi][ni], afh[mi], &bfl[ni >> 1][(ni & 1) * 2]);
#pragma unroll
            for (int mi = 0; mi < MI; mi++)
#pragma unroll
                for (int ni = 0; ni < NI; ni++)
                    mma_bf16(acc[mi][ni], afl[mi], &bfh[ni >> 1][(ni & 1) * 2]);
        }
    }

    const int g = lid >> 2, t = lid & 3;
#pragma unroll
    for (int mi = 0; mi < MI; mi++) {
#pragma unroll
        for (int ni = 0; ni < NI; ni++) {
            int row0 = brow + warp_row + mi * 16 + g;
            int row1 = row0 + 8;
            int col  = bn0 + warp_col + ni * 8 + 2 * t;
            const float* a = acc[mi][ni];
            if (EPI == 0) {
                float bv0 = ev1[col], bv1 = ev1[col + 1];
                float s0 = ev0[col], s1 = ev0[col + 1];
                float x00 = a[0] + bv0, x01 = a[1] + bv1;
                float x10 = a[2] + bv0, x11 = a[3] + bv1;
                float2 r0 = make_float2(s0 / (1.f + expf(-x00)), s1 / (1.f + expf(-x01)));
                float2 r1 = make_float2(s0 / (1.f + expf(-x10)), s1 / (1.f + expf(-x11)));
                *(float2*)(g_schi + (size_t)row0 * RANK + col) = r0;
                *(float2*)(g_schi + (size_t)row1 * RANK + col) = r1;
            } else {
                float b0 = 2.f * ev0[col], b1 = 2.f * ev0[col + 1];
                float2 r0 = make_float2(fmaxf(a[0] + b0, 0.f), fmaxf(a[1] + b1, 0.f));
                float2 r1 = make_float2(fmaxf(a[2] + b0, 0.f), fmaxf(a[3] + b1, 0.f));
                *(float2*)(outp + (size_t)row0 * UNITS + col) = r0;
                *(float2*)(outp + (size_t)row1 * UNITS + col) = r1;
            }
        }
    }
}

// ---------------------------------------------------------------------------
// GEMM1 fused: 64x128 tile, 128 threads (1x4 warps), MI=4, K-split x2.
// ---------------------------------------------------------------------------
__global__ __launch_bounds__(128, 3)
void gemm1_fused(const float* __restrict__ Afp)
{
    constexpr int KTOT = N_IN;
    constexpr int KSEG = KTOT / 2;       // 2048
    constexpr int NC = KSEG / 32;        // 64
    constexpr int AHB = 64 * 40 * 2;     // 5120
    constexpr int ABUF = 2 * AHB;        // 10240
    constexpr int BHB = 128 * 40 * 2;    // 10240
    constexpr int BSTG = 2 * BHB;        // 20480

    extern __shared__ char smem[];
    const uint32_t sb = smem_to_u32(smem);
    const uint32_t sbB = sb + 2 * ABUF;

    const int tid = threadIdx.x;
    const int wid = tid >> 5, lid = tid & 31;
    const int wn = wid;
    const int warp_col = wn * 32;
    const int brow = blockIdx.y * 64;
    const int bn0  = blockIdx.x * 128;
    const int kseg = blockIdx.z;
    const int koff = kseg * KSEG;

    float acc[4][4][4];
#pragma unroll
    for (int mi = 0; mi < 4; mi++)
#pragma unroll
        for (int ni = 0; ni < 4; ni++)
#pragma unroll
            for (int q = 0; q < 4; q++) acc[mi][ni][q] = 0.f;

    const uint32_t a_lane = (uint32_t)(((lid & 15) * 40 + (lid >> 4) * 8) * 2);
    const uint32_t b_lane = (uint32_t)((((lid & 7) + ((lid >> 4) << 3)) * 40 +
                                        ((lid >> 3) & 1) * 8) * 2);

    auto ldgA = [&](int k0, float4* pf) {
#pragma unroll
        for (int it = 0; it < 4; it++) {
            int flat = it * 128 + tid;
            int row = flat >> 3, seg = flat & 7;
            pf[it] = *(const float4*)(Afp + (size_t)(brow + row) * KTOT + k0 + seg * 4);
        }
    };
    auto cvtA = [&](int s, const float4* pf) {
        uint32_t base = (uint32_t)(s * ABUF);
#pragma unroll
        for (int it = 0; it < 4; it++) {
            int flat = it * 128 + tid;
            int row = flat >> 3, seg = flat & 7;
            ushort4 h, l;
            split2(pf[it].x, h.x, l.x);
            split2(pf[it].y, h.y, l.y);
            split2(pf[it].z, h.z, l.z);
            split2(pf[it].w, h.w, l.w);
            uint32_t off = base + (uint32_t)(row * 80 + seg * 8);
            *(ushort4*)(smem + off) = h;
            *(ushort4*)(smem + off + AHB) = l;
        }
    };
    auto loadB = [&](int s, int k0) {
        uint32_t st = sbB + (uint32_t)(s * BSTG);
#pragma unroll
        for (int it = 0; it < 4; it++) {
            int flat = it * 128 + tid;
            int row = flat >> 2, seg = flat & 3;
            uint32_t off = (uint32_t)(row * 80 + seg * 16);
            size_t gi = (size_t)(bn0 + row) * KTOT + k0 + seg * 8;
            CP_ASYNC16(st + off, g_Ut_hi + gi);
            CP_ASYNC16(st + BHB + off, g_Ut_lo + gi);
        }
    };

    // prologue
    float4 pf_cur[4], pf_nxt[4];
    ldgA(koff, pf_cur);
    cvtA(0, pf_cur);
    ldgA(koff + 32, pf_cur);
    loadB(0, koff);
    CP_COMMIT();

    for (int ch = 0; ch < NC; ch++) {
        cp_wait_group<0>();
        __syncthreads();

        if (ch + 2 < NC) ldgA(koff + (ch + 2) * 32, pf_nxt);
        if (ch + 1 < NC) {
            cvtA((ch + 1) & 1, pf_cur);
            loadB((ch + 1) & 1, koff + (ch + 1) * 32);
        }
        CP_COMMIT();

        const uint32_t Ah = sb + (uint32_t)((ch & 1) * ABUF);
        const uint32_t Al = Ah + AHB;
        const uint32_t Bh = sbB + (uint32_t)((ch & 1) * BSTG);
        const uint32_t Bl = Bh + BHB;
#pragma unroll
        for (int ks = 0; ks < 2; ks++) {
            uint32_t afh[4][4], afl[4][4], bfh[2][4], bfl[2][4];
#pragma unroll
            for (int mi = 0; mi < 4; mi++) {
                uint32_t ao = a_lane + (uint32_t)((mi * 16) * 80 + ks * 32);
                ldmx4(afh[mi], Ah + ao);
                ldmx4(afl[mi], Al + ao);
            }
#pragma unroll
            for (int j = 0; j < 2; j++) {
                uint32_t bo = b_lane + (uint32_t)((warp_col + j * 16) * 80 + ks * 32);
                ldmx4(bfh[j], Bh + bo);
                ldmx4(bfl[j], Bl + bo);
            }
#pragma unroll
            for (int mi = 0; mi < 4; mi++)
#pragma unroll
                for (int ni = 0; ni < 4; ni++)
                    mma_bf16(acc[mi][ni], afh[mi], &bfh[ni >> 1][(ni & 1) * 2]);
#pragma unroll
            for (int mi = 0; mi < 4; mi++)
#pragma unroll
                for (int ni = 0; ni < 4; ni++)
                    mma_bf16(acc[mi][ni], afh[mi], &bfl[ni >> 1][(ni & 1) * 2]);
#pragma unroll
            for (int mi = 0; mi < 4; mi++)
#pragma unroll
                for (int ni = 0; ni < 4; ni++)
                    mma_bf16(acc[mi][ni], afl[mi], &bfh[ni >> 1][(ni & 1) * 2]);
        }
#pragma unroll
        for (int q = 0; q < 4; q++) pf_cur[q] = pf_nxt[q];
    }

    // epilogue: fp32 partial -> g_part[kseg]
    float* dst = &g_part[kseg][0];
    const int g = lid >> 2, t = lid & 3;
#pragma unroll
    for (int mi = 0; mi < 4; mi++) {
#pragma unroll
        for (int ni = 0; ni < 4; ni++) {
            int row0 = brow + mi * 16 + g;
            int row1 = row0 + 8;
            int col  = bn0 + warp_col + ni * 8 + 2 * t;
            const float* a = acc[mi][ni];
            *(float2*)(dst + (size_t)row0 * RANK + col) = make_float2(a[0], a[1]);
            *(float2*)(dst + (size_t)row1 * RANK + col) = make_float2(a[2], a[3]);
        }
    }
}

// ---------------------------------------------------------------------------
// k_finish: t = (p0 + p1) * schi -> g_t hi/lo
// ---------------------------------------------------------------------------
__global__ __launch_bounds__(256)
void k_finish()
{
    size_t i = ((size_t)blockIdx.x * 256 + threadIdx.x) * 4;
    float4 p0 = *(const float4*)(&g_part[0][i]);
    float4 p1 = *(const float4*)(&g_part[1][i]);
    float4 sc = *(const float4*)(g_schi + i);
    float4 t;
    t.x = (p0.x + p1.x) * sc.x;
    t.y = (p0.y + p1.y) * sc.y;
    t.z = (p0.z + p1.z) * sc.z;
    t.w = (p0.w + p1.w) * sc.w;
    ushort4 h, l;
    split2(t.x, h.x, l.x);
    split2(t.y, h.y, l.y);
    split2(t.z, h.z, l.z);
    split2(t.w, h.w, l.w);
    *(ushort4*)(g_t_hi + i) = h;
    *(ushort4*)(g_t_lo + i) = l;
}

// ---------------------------------------------------------------------------
// Launch: fork/join streams so prep1+chi overlap prep2+gemm1.
//   stream0: prep1 -> chi ............ waits sB ... finish -> gemm2
//   sB:      prep2 -> gemm1 -> (event)
// Streams/events created lazily on first (correctness) call; reused during
// graph capture. All CUDA objects are host-side (no device allocation).
// ---------------------------------------------------------------------------
extern "C" void kernel_launch(void* const* d_in, const int* in_sizes, int n_in,
                              void* d_out, int out_size)
{
    const float* inputs  = (const float*)d_in[0];
    const float* context = (const float*)d_in[1];
    const float* U       = (const float*)d_in[2];
    const float* S       = (const float*)d_in[3];
    const float* V       = (const float*)d_in[4];
    const float* W       = (const float*)d_in[5];
    const float* Bvec    = (const float*)d_in[6];
    const float* bias    = (const float*)d_in[7];
    float* out = (float*)d_out;

    static cudaStream_t sB = nullptr;
    static cudaEvent_t  eFork = nullptr, eJoin = nullptr;
    if (!sB) {
        cudaStreamCreateWithFlags(&sB, cudaStreamNonBlocking);
        cudaEventCreateWithFlags(&eFork, cudaEventDisableTiming);
        cudaEventCreateWithFlags(&eJoin, cudaEventDisableTiming);
    }

    const int smem_chi = 4 * (128 + 64) * 160;      // 122880
    const int smem_g1  = 2 * 10240 + 2 * 20480;     // 61440 -> 3 CTAs/SM
    const int smem_g2  = 2 * (64 + 128) * 160;      // 61440 -> 3 CTAs/SM

    cudaFuncSetAttribute(mma_gemm<128, 64, 4, 2, 512, 0, 4, 1>,
                         cudaFuncAttributeMaxDynamicSharedMemorySize, smem_chi);
    cudaFuncSetAttribute(gemm1_fused,
                         cudaFuncAttributeMaxDynamicSharedMemorySize, smem_g1);
    cudaFuncSetAttribute(mma_gemm<64, 128, 1, 4, 256, 2, 2, 3>,
                         cudaFuncAttributeMaxDynamicSharedMemorySize, smem_g2);

    // Fork: sB branch handles prep2 -> gemm1 (independent of chi chain)
    cudaEventRecord(eFork, 0);
    cudaStreamWaitEvent(sB, eFork, 0);

    // Branch B (sB): prep2 (V split + U transpose), then gemm1
    prep2<<<1024 + 1024, 256, 0, sB>>>(V, U);
    gemm1_fused<<<dim3(RANK / 128, B_SZ / 64, 2), 128, smem_g1, sB>>>(inputs);
    cudaEventRecord(eJoin, sB);

    // Branch A (stream 0): prep1 (ctx split + W transpose), then chi
    prep1<<<2048 + 128, 256>>>(context, W);
    mma_gemm<128, 64, 4, 2, 512, 0, 4, 1><<<dim3(RANK / 64, B_SZ / 128), 256, smem_chi>>>(
        nullptr, S, Bvec);

    // Join: finish needs schi (branch A) + partials (branch B)
    cudaStreamWaitEvent(0, eJoin, 0);
    k_finish<<<(B_SZ * RANK) / 1024, 256>>>();
    // gemm2: out = relu(t @ V^T + 2*bias)
    mma_gemm<64, 128, 1, 4, 256, 2, 2, 3><<<dim3(UNITS / 128, B_SZ / 64), 128, smem_g2>>>(
        out, bias, nullptr);
}

// round 16
// speedup vs baseline: 1.6397x; 1.6397x over previous
#include <cuda_runtime.h>
#include <cuda_bf16.h>
#include <cstdint>
#include <math.h>

// Problem dims (fixed)
#define B_SZ   4096
#define N_IN   4096
#define N_CTX  512
#define UNITS  4096
#define RANK   256

// ---------------------------------------------------------------------------
// Device scratch
// ---------------------------------------------------------------------------
__device__ __align__(16) unsigned short g_ctx_hi[B_SZ * N_CTX];
__device__ __align__(16) unsigned short g_ctx_lo[B_SZ * N_CTX];
__device__ __align__(16) unsigned short g_t_hi[B_SZ * RANK];
__device__ __align__(16) unsigned short g_t_lo[B_SZ * RANK];
__device__ __align__(16) unsigned short g_Ut_hi[RANK * N_IN];   // U^T [256][4096]
__device__ __align__(16) unsigned short g_Ut_lo[RANK * N_IN];
__device__ __align__(16) unsigned short g_V_hi[UNITS * RANK];
__device__ __align__(16) unsigned short g_V_lo[UNITS * RANK];
__device__ __align__(16) unsigned short g_Wt_hi[RANK * N_CTX];  // W^T [256][512]
__device__ __align__(16) unsigned short g_Wt_lo[RANK * N_CTX];
__device__ __align__(16) float          g_schi[B_SZ * RANK];
__device__ __align__(16) float          g_part[2][B_SZ * RANK];

// ---------------------------------------------------------------------------
// Helpers
// ---------------------------------------------------------------------------
__device__ __forceinline__ uint32_t smem_to_u32(const void* p) {
    uint32_t a;
    asm("{ .reg .u64 t; cvta.to.shared.u64 t, %1; cvt.u32.u64 %0, t; }"
        : "=r"(a) : "l"(p));
    return a;
}

__device__ __forceinline__ void ldmx4(uint32_t* r, uint32_t addr) {
    asm volatile("ldmatrix.sync.aligned.m8n8.x4.shared.b16 {%0,%1,%2,%3}, [%4];\n"
                 : "=r"(r[0]), "=r"(r[1]), "=r"(r[2]), "=r"(r[3]) : "r"(addr));
}

__device__ __forceinline__ void mma_bf16(float* c, const uint32_t* a, const uint32_t* b) {
    asm volatile(
        "mma.sync.aligned.m16n8k16.row.col.f32.bf16.bf16.f32 "
        "{%0,%1,%2,%3}, {%4,%5,%6,%7}, {%8,%9}, {%0,%1,%2,%3};\n"
        : "+f"(c[0]), "+f"(c[1]), "+f"(c[2]), "+f"(c[3])
        : "r"(a[0]), "r"(a[1]), "r"(a[2]), "r"(a[3]), "r"(b[0]), "r"(b[1]));
}

#define CP_ASYNC16(saddr, gptr) \
    asm volatile("cp.async.cg.shared.global [%0], [%1], 16;\n" \
                 :: "r"(saddr), "l"(gptr))
#define CP_COMMIT() asm volatile("cp.async.commit_group;\n" ::: "memory")

template <int N>
__device__ __forceinline__ void cp_wait_group() {
    asm volatile("cp.async.wait_group %0;\n" :: "n"(N) : "memory");
}

__device__ __forceinline__ void split2(float x, unsigned short& h, unsigned short& l) {
    __nv_bfloat16 hb = __float2bfloat16_rn(x);
    h = *reinterpret_cast<unsigned short*>(&hb);
    float r = x - __bfloat162float(hb);
    __nv_bfloat16 lb = __float2bfloat16_rn(r);
    l = *reinterpret_cast<unsigned short*>(&lb);
}

// ---------------------------------------------------------------------------
// Merged prep kernel: all four conversions in one launch.
//   blocks [0,2048):      ctx split      -> g_ctx hi/lo
//   blocks [2048,2176):   W transpose    -> g_Wt  hi/lo
//   blocks [2176,3200):   V split        -> g_V   hi/lo
//   blocks [3200,4224):   U transpose    -> g_Ut  hi/lo
// ---------------------------------------------------------------------------
__global__ __launch_bounds__(256)
void prep_all(const float* __restrict__ ctx, const float* __restrict__ W,
              const float* __restrict__ V, const float* __restrict__ U)
{
    __shared__ float tile[32][33];
    int b = blockIdx.x, tid = threadIdx.x;
    if (b < 2048) {
        size_t i = ((size_t)b * 256 + tid) * 4;
        float4 v = *(const float4*)(ctx + i);
        ushort4 h, l;
        split2(v.x, h.x, l.x); split2(v.y, h.y, l.y);
        split2(v.z, h.z, l.z); split2(v.w, h.w, l.w);
        *(ushort4*)(g_ctx_hi + i) = h;
        *(ushort4*)(g_ctx_lo + i) = l;
    } else if (b < 2176) {
        int bb = b - 2048;                 // W: R=512, C=256
        int c0 = (bb & 7) * 32;
        int r0 = (bb >> 3) * 32;
        int tx = tid & 31, ty = tid >> 5;
        for (int i = ty; i < 32; i += 8)
            tile[i][tx] = W[(size_t)(r0 + i) * RANK + c0 + tx];
        __syncthreads();
        for (int i = ty; i < 32; i += 8) {
            int c = c0 + i, r = r0 + tx;
            unsigned short h, l;
            split2(tile[tx][i], h, l);
            g_Wt_hi[(size_t)c * N_CTX + r] = h;
            g_Wt_lo[(size_t)c * N_CTX + r] = l;
        }
    } else if (b < 3200) {
        int bb = b - 2176;
        size_t i = ((size_t)bb * 256 + tid) * 4;
        float4 v = *(const float4*)(V + i);
        ushort4 h, l;
        split2(v.x, h.x, l.x); split2(v.y, h.y, l.y);
        split2(v.z, h.z, l.z); split2(v.w, h.w, l.w);
        *(ushort4*)(g_V_hi + i) = h;
        *(ushort4*)(g_V_lo + i) = l;
    } else {
        int bb = b - 3200;                 // U: R=4096, C=256
        int c0 = (bb & 7) * 32;
        int r0 = (bb >> 3) * 32;
        int tx = tid & 31, ty = tid >> 5;
        for (int i = ty; i < 32; i += 8)
            tile[i][tx] = U[(size_t)(r0 + i) * RANK + c0 + tx];
        __syncthreads();
        for (int i = ty; i < 32; i += 8) {
            int c = c0 + i, r = r0 + tx;
            unsigned short h, l;
            split2(tile[tx][i], h, l);
            g_Ut_hi[(size_t)c * N_IN + r] = h;
            g_Ut_lo[(size_t)c * N_IN + r] = l;
        }
    }
}

// ---------------------------------------------------------------------------
// Template GEMM (pre-split A). EPI 0 (chi) and 2 (out).
// Per-accumulator MMA order (R12 best).
// ---------------------------------------------------------------------------
template <int TILEM, int TILEN, int WARPS_M, int WARPS_N, int KTOT, int EPI,
          int STAGES, int MINCTA>
__global__ __launch_bounds__(WARPS_M * WARPS_N * 32, MINCTA)
void mma_gemm(float* __restrict__ outp,
              const float* __restrict__ ev0,   // EPI0: S, EPI2: bias
              const float* __restrict__ ev1)   // EPI0: Bvec
{
    constexpr int THREADS = WARPS_M * WARPS_N * 32;
    constexpr int WM = TILEM / WARPS_M;
    constexpr int MI = WM / 16;
    constexpr int NI = 4;
    constexpr int AHB = TILEM * 40 * 2;
    constexpr int BHB = TILEN * 40 * 2;
    constexpr int STG = 2 * AHB + 2 * BHB;
    constexpr int NC  = KTOT / 32;
    constexpr int A_IT = TILEM * 4 / THREADS;
    constexpr int B_IT = TILEN * 4 / THREADS;
    static_assert(WARPS_N * 32 == TILEN, "tile mismatch");

    extern __shared__ char smem[];
    const uint32_t sb = smem_to_u32(smem);

    const int tid = threadIdx.x;
    const int wid = tid >> 5, lid = tid & 31;
    const int wm = wid / WARPS_N, wn = wid % WARPS_N;
    const int warp_row = wm * WM;
    const int warp_col = wn * 32;
    const int brow = blockIdx.y * TILEM;
    const int bn0  = blockIdx.x * TILEN;

    const unsigned short* Ahg = (EPI == 0) ? g_ctx_hi : g_t_hi;
    const unsigned short* Alg = (EPI == 0) ? g_ctx_lo : g_t_lo;
    const unsigned short* Bhg = (EPI == 0) ? g_Wt_hi : g_V_hi;
    const unsigned short* Blg = (EPI == 0) ? g_Wt_lo : g_V_lo;

    float acc[MI][NI][4];
#pragma unroll
    for (int mi = 0; mi < MI; mi++)
#pragma unroll
        for (int ni = 0; ni < NI; ni++)
#pragma unroll
            for (int q = 0; q < 4; q++) acc[mi][ni][q] = 0.f;

    const uint32_t a_lane = (uint32_t)(((lid & 15) * 40 + (lid >> 4) * 8) * 2);
    const uint32_t b_lane = (uint32_t)((((lid & 7) + ((lid >> 4) << 3)) * 40 +
                                        ((lid >> 3) & 1) * 8) * 2);

    auto load_stage = [&](int s, int k0) {
        const uint32_t st = sb + (uint32_t)(s * STG);
#pragma unroll
        for (int it = 0; it < A_IT; it++) {
            int flat = it * THREADS + tid;
            int row = flat >> 2, seg = flat & 3;
            uint32_t off = (uint32_t)(row * 80 + seg * 16);
            size_t gi = (size_t)(brow + row) * KTOT + k0 + seg * 8;
            CP_ASYNC16(st + off, Ahg + gi);
            CP_ASYNC16(st + AHB + off, Alg + gi);
        }
#pragma unroll
        for (int it = 0; it < B_IT; it++) {
            int flat = it * THREADS + tid;
            int row = flat >> 2, seg = flat & 3;
            uint32_t off = (uint32_t)(row * 80 + seg * 16);
            size_t gi = (size_t)(bn0 + row) * KTOT + k0 + seg * 8;
            CP_ASYNC16(st + 2 * AHB + off, Bhg + gi);
            CP_ASYNC16(st + 2 * AHB + BHB + off, Blg + gi);
        }
    };

#pragma unroll
    for (int s = 0; s < STAGES - 1; s++) {
        load_stage(s, s * 32);
        CP_COMMIT();
    }

    for (int ch = 0; ch < NC; ch++) {
        cp_wait_group<STAGES - 2>();
        __syncthreads();

        if (ch + STAGES - 1 < NC)
            load_stage((ch + STAGES - 1) % STAGES, (ch + STAGES - 1) * 32);
        CP_COMMIT();

        const uint32_t cb = sb + (uint32_t)((ch % STAGES) * STG);
        const uint32_t Ah = cb, Al = cb + AHB, Bh = cb + 2 * AHB, Bl = Bh + BHB;
#pragma unroll
        for (int ks = 0; ks < 2; ks++) {
            uint32_t afh[MI][4], afl[MI][4], bfh[2][4], bfl[2][4];
#pragma unroll
            for (int mi = 0; mi < MI; mi++) {
                uint32_t ao = a_lane + (uint32_t)((warp_row + mi * 16) * 80 + ks * 32);
                ldmx4(afh[mi], Ah + ao);
                ldmx4(afl[mi], Al + ao);
            }
#pragma unroll
            for (int j = 0; j < 2; j++) {
                uint32_t bo = b_lane + (uint32_t)((warp_col + j * 16) * 80 + ks * 32);
                ldmx4(bfh[j], Bh + bo);
                ldmx4(bfl[j], Bl + bo);
            }
#pragma unroll
            for (int mi = 0; mi < MI; mi++) {
#pragma unroll
                for (int ni = 0; ni < NI; ni++) {
                    const uint32_t* bh = &bfh[ni >> 1][(ni & 1) * 2];
                    const uint32_t* bl = &bfl[ni >> 1][(ni & 1) * 2];
                    mma_bf16(acc[mi][ni], afh[mi], bh);
                    mma_bf16(acc[mi][ni], afh[mi], bl);
                    mma_bf16(acc[mi][ni], afl[mi], bh);
                }
            }
        }
    }

    const int g = lid >> 2, t = lid & 3;
#pragma unroll
    for (int mi = 0; mi < MI; mi++) {
#pragma unroll
        for (int ni = 0; ni < NI; ni++) {
            int row0 = brow + warp_row + mi * 16 + g;
            int row1 = row0 + 8;
            int col  = bn0 + warp_col + ni * 8 + 2 * t;
            const float* a = acc[mi][ni];
            if (EPI == 0) {
                float bv0 = ev1[col], bv1 = ev1[col + 1];
                float s0 = ev0[col], s1 = ev0[col + 1];
                float x00 = a[0] + bv0, x01 = a[1] + bv1;
                float x10 = a[2] + bv0, x11 = a[3] + bv1;
                float2 r0 = make_float2(s0 / (1.f + expf(-x00)), s1 / (1.f + expf(-x01)));
                float2 r1 = make_float2(s0 / (1.f + expf(-x10)), s1 / (1.f + expf(-x11)));
                *(float2*)(g_schi + (size_t)row0 * RANK + col) = r0;
                *(float2*)(g_schi + (size_t)row1 * RANK + col) = r1;
            } else {
                float b0 = 2.f * ev0[col], b1 = 2.f * ev0[col + 1];
                float2 r0 = make_float2(fmaxf(a[0] + b0, 0.f), fmaxf(a[1] + b1, 0.f));
                float2 r1 = make_float2(fmaxf(a[2] + b0, 0.f), fmaxf(a[3] + b1, 0.f));
                *(float2*)(outp + (size_t)row0 * UNITS + col) = r0;
                *(float2*)(outp + (size_t)row1 * UNITS + col) = r1;
            }
        }
    }
}

// ---------------------------------------------------------------------------
// GEMM1 fused (R12 config): 64x128 tile, 128 threads (1x4 warps), MI=4,
//   K-split x2, B 4-stage cp.async, A LDG->convert->STS 2-stage.
//   smem 102400 -> 2 CTAs/SM.
// ---------------------------------------------------------------------------
__global__ __launch_bounds__(128, 2)
void gemm1_fused(const float* __restrict__ Afp)
{
    constexpr int KTOT = N_IN;
    constexpr int KSEG = KTOT / 2;       // 2048
    constexpr int NC = KSEG / 32;        // 64
    constexpr int AHB = 64 * 40 * 2;     // 5120
    constexpr int ABUF = 2 * AHB;        // 10240
    constexpr int BHB = 128 * 40 * 2;    // 10240
    constexpr int BSTG = 2 * BHB;        // 20480
    constexpr int BSTAGES = 4;

    extern __shared__ char smem[];
    const uint32_t sb = smem_to_u32(smem);
    const uint32_t sbB = sb + 2 * ABUF;

    const int tid = threadIdx.x;
    const int wid = tid >> 5, lid = tid & 31;
    const int wn = wid;
    const int warp_col = wn * 32;
    const int brow = blockIdx.y * 64;
    const int bn0  = blockIdx.x * 128;
    const int kseg = blockIdx.z;
    const int koff = kseg * KSEG;

    float acc[4][4][4];
#pragma unroll
    for (int mi = 0; mi < 4; mi++)
#pragma unroll
        for (int ni = 0; ni < 4; ni++)
#pragma unroll
            for (int q = 0; q < 4; q++) acc[mi][ni][q] = 0.f;

    const uint32_t a_lane = (uint32_t)(((lid & 15) * 40 + (lid >> 4) * 8) * 2);
    const uint32_t b_lane = (uint32_t)((((lid & 7) + ((lid >> 4) << 3)) * 40 +
                                        ((lid >> 3) & 1) * 8) * 2);

    auto ldgA = [&](int k0, float4* pf) {
#pragma unroll
        for (int it = 0; it < 4; it++) {
            int flat = it * 128 + tid;
            int row = flat >> 3, seg = flat & 7;
            pf[it] = *(const float4*)(Afp + (size_t)(brow + row) * KTOT + k0 + seg * 4);
        }
    };
    auto cvtA = [&](int s, const float4* pf) {
        uint32_t base = (uint32_t)(s * ABUF);
#pragma unroll
        for (int it = 0; it < 4; it++) {
            int flat = it * 128 + tid;
            int row = flat >> 3, seg = flat & 7;
            ushort4 h, l;
            split2(pf[it].x, h.x, l.x);
            split2(pf[it].y, h.y, l.y);
            split2(pf[it].z, h.z, l.z);
            split2(pf[it].w, h.w, l.w);
            uint32_t off = base + (uint32_t)(row * 80 + seg * 8);
            *(ushort4*)(smem + off) = h;
            *(ushort4*)(smem + off + AHB) = l;
        }
    };
    auto loadB = [&](int s, int k0) {
        uint32_t st = sbB + (uint32_t)(s * BSTG);
#pragma unroll
        for (int it = 0; it < 4; it++) {
            int flat = it * 128 + tid;
            int row = flat >> 2, seg = flat & 3;
            uint32_t off = (uint32_t)(row * 80 + seg * 16);
            size_t gi = (size_t)(bn0 + row) * KTOT + k0 + seg * 8;
            CP_ASYNC16(st + off, g_Ut_hi + gi);
            CP_ASYNC16(st + BHB + off, g_Ut_lo + gi);
        }
    };

    // prologue
    float4 pf_cur[4], pf_nxt[4];
    ldgA(koff, pf_cur);
    cvtA(0, pf_cur);
    ldgA(koff + 32, pf_cur);
#pragma unroll
    for (int s = 0; s < BSTAGES - 1; s++) {
        loadB(s, koff + s * 32);
        CP_COMMIT();
    }

    for (int ch = 0; ch < NC; ch++) {
        cp_wait_group<BSTAGES - 2>();
        __syncthreads();

        if (ch + 2 < NC) ldgA(koff + (ch + 2) * 32, pf_nxt);
        if (ch + 1 < NC) cvtA((ch + 1) & 1, pf_cur);
        if (ch + BSTAGES - 1 < NC)
            loadB((ch + BSTAGES - 1) % BSTAGES, koff + (ch + BSTAGES - 1) * 32);
        CP_COMMIT();

        const uint32_t Ah = sb + (uint32_t)((ch & 1) * ABUF);
        const uint32_t Al = Ah + AHB;
        const uint32_t Bh = sbB + (uint32_t)((ch % BSTAGES) * BSTG);
        const uint32_t Bl = Bh + BHB;
#pragma unroll
        for (int ks = 0; ks < 2; ks++) {
            uint32_t afh[4][4], afl[4][4], bfh[2][4], bfl[2][4];
#pragma unroll
            for (int mi = 0; mi < 4; mi++) {
                uint32_t ao = a_lane + (uint32_t)((mi * 16) * 80 + ks * 32);
                ldmx4(afh[mi], Ah + ao);
                ldmx4(afl[mi], Al + ao);
            }
#pragma unroll
            for (int j = 0; j < 2; j++) {
                uint32_t bo = b_lane + (uint32_t)((warp_col + j * 16) * 80 + ks * 32);
                ldmx4(bfh[j], Bh + bo);
                ldmx4(bfl[j], Bl + bo);
            }
#pragma unroll
            for (int mi = 0; mi < 4; mi++) {
#pragma unroll
                for (int ni = 0; ni < 4; ni++) {
                    const uint32_t* bh = &bfh[ni >> 1][(ni & 1) * 2];
                    const uint32_t* bl = &bfl[ni >> 1][(ni & 1) * 2];
                    mma_bf16(acc[mi][ni], afh[mi], bh);
                    mma_bf16(acc[mi][ni], afh[mi], bl);
                    mma_bf16(acc[mi][ni], afl[mi], bh);
                }
            }
        }
#pragma unroll
        for (int q = 0; q < 4; q++) pf_cur[q] = pf_nxt[q];
    }

    // epilogue: fp32 partial -> g_part[kseg]
    float* dst = &g_part[kseg][0];
    const int g = lid >> 2, t = lid & 3;
#pragma unroll
    for (int mi = 0; mi < 4; mi++) {
#pragma unroll
        for (int ni = 0; ni < 4; ni++) {
            int row0 = brow + mi * 16 + g;
            int row1 = row0 + 8;
            int col  = bn0 + warp_col + ni * 8 + 2 * t;
            const float* a = acc[mi][ni];
            *(float2*)(dst + (size_t)row0 * RANK + col) = make_float2(a[0], a[1]);
            *(float2*)(dst + (size_t)row1 * RANK + col) = make_float2(a[2], a[3]);
        }
    }
}

// ---------------------------------------------------------------------------
// k_finish: t = (p0 + p1) * schi -> g_t hi/lo
// ---------------------------------------------------------------------------
__global__ __launch_bounds__(256)
void k_finish()
{
    size_t i = ((size_t)blockIdx.x * 256 + threadIdx.x) * 4;
    float4 p0 = *(const float4*)(&g_part[0][i]);
    float4 p1 = *(const float4*)(&g_part[1][i]);
    float4 sc = *(const float4*)(g_schi + i);
    float4 t;
    t.x = (p0.x + p1.x) * sc.x;
    t.y = (p0.y + p1.y) * sc.y;
    t.z = (p0.z + p1.z) * sc.z;
    t.w = (p0.w + p1.w) * sc.w;
    ushort4 h, l;
    split2(t.x, h.x, l.x);
    split2(t.y, h.y, l.y);
    split2(t.z, h.z, l.z);
    split2(t.w, h.w, l.w);
    *(ushort4*)(g_t_hi + i) = h;
    *(ushort4*)(g_t_lo + i) = l;
}

// ---------------------------------------------------------------------------
// Launch (single stream, R12 structure with merged prep).
// ---------------------------------------------------------------------------
extern "C" void kernel_launch(void* const* d_in, const int* in_sizes, int n_in,
                              void* d_out, int out_size)
{
    const float* inputs  = (const float*)d_in[0];
    const float* context = (const float*)d_in[1];
    const float* U       = (const float*)d_in[2];
    const float* S       = (const float*)d_in[3];
    const float* V       = (const float*)d_in[4];
    const float* W       = (const float*)d_in[5];
    const float* Bvec    = (const float*)d_in[6];
    const float* bias    = (const float*)d_in[7];
    float* out = (float*)d_out;

    const int smem_chi = 4 * (128 + 64) * 160;      // 122880
    const int smem_g1  = 2 * 10240 + 4 * 20480;     // 102400 -> 2 CTAs/SM
    const int smem_g2  = 2 * (128 + 128) * 160;     // 81920  -> 2 CTAs/SM

    cudaFuncSetAttribute(mma_gemm<128, 64, 4, 2, 512, 0, 4, 1>,
                         cudaFuncAttributeMaxDynamicSharedMemorySize, smem_chi);
    cudaFuncSetAttribute(gemm1_fused,
                         cudaFuncAttributeMaxDynamicSharedMemorySize, smem_g1);
    cudaFuncSetAttribute(mma_gemm<128, 128, 2, 4, 256, 2, 2, 2>,
                         cudaFuncAttributeMaxDynamicSharedMemorySize, smem_g2);

    // launch 0: all conversions fused
    prep_all<<<4224, 256>>>(context, W, V, U);
    // launch 1: chi = S*sigmoid(context @ W^T + B)
    mma_gemm<128, 64, 4, 2, 512, 0, 4, 1><<<dim3(RANK / 64, B_SZ / 128), 256, smem_chi>>>(
        nullptr, S, Bvec);
    // launch 2: gemm1 (K-split x2)
    gemm1_fused<<<dim3(RANK / 128, B_SZ / 64, 2), 128, smem_g1>>>(inputs);
    // launch 3: finish (reduce partials, scale by schi, split to bf16)
    k_finish<<<(B_SZ * RANK) / 1024, 256>>>();
    // launch 4: out = relu(t @ V^T + 2*bias)
    mma_gemm<128, 128, 2, 4, 256, 2, 2, 2><<<dim3(UNITS / 128, B_SZ / 128), 256, smem_g2>>>(
        out, bias, nullptr);
}

// round 17
// speedup vs baseline: 1.8776x; 1.1451x over previous
#include <cuda_runtime.h>
#include <cuda_bf16.h>
#include <cstdint>
#include <math.h>

// Problem dims (fixed)
#define B_SZ   4096
#define N_IN   4096
#define N_CTX  512
#define UNITS  4096
#define RANK   256

// ---------------------------------------------------------------------------
// Device scratch — all operands fp32 bit-patterns holding tf32-rounded values,
// stored in MMA-fragment order (see fragA_idx / fragB_idx).
// ---------------------------------------------------------------------------
__device__ __align__(16) float g_ctx_f[B_SZ * N_CTX];   // A-frag order, K=512
__device__ __align__(16) float g_t_f[B_SZ * RANK];      // A-frag order, K=256
__device__ __align__(16) float g_Ut_f[RANK * N_IN];     // B-frag order, K=4096
__device__ __align__(16) float g_V_f[UNITS * RANK];     // B-frag order, K=256
__device__ __align__(16) float g_Wt_f[RANK * N_CTX];    // B-frag order, K=512
__device__ __align__(16) float g_schi[B_SZ * RANK];     // A-frag order (elementwise)
__device__ __align__(16) float g_part[2][B_SZ * RANK];  // A-frag order (elementwise)

// ---------------------------------------------------------------------------
// Helpers
// ---------------------------------------------------------------------------
__device__ __forceinline__ uint32_t smem_to_u32(const void* p) {
    uint32_t a;
    asm("{ .reg .u64 t; cvta.to.shared.u64 t, %1; cvt.u32.u64 %0, t; }"
        : "=r"(a) : "l"(p));
    return a;
}

__device__ __forceinline__ float to_tf32f(float x) {
    uint32_t r;
    asm("cvt.rna.tf32.f32 %0, %1;" : "=r"(r) : "f"(x));
    return __uint_as_float(r);
}

__device__ __forceinline__ void lds128(uint32_t* r, uint32_t a) {
    asm volatile("ld.shared.v4.b32 {%0,%1,%2,%3}, [%4];"
                 : "=r"(r[0]), "=r"(r[1]), "=r"(r[2]), "=r"(r[3]) : "r"(a));
}
__device__ __forceinline__ void lds64(uint32_t* r, uint32_t a) {
    asm volatile("ld.shared.v2.b32 {%0,%1}, [%2];"
                 : "=r"(r[0]), "=r"(r[1]) : "r"(a));
}

// m16n8k8 tf32 mma: A 4 regs, B 2 regs, C 4 floats
__device__ __forceinline__ void mma_tf32(float* c, const uint32_t* a, const uint32_t* b) {
    asm volatile(
        "mma.sync.aligned.m16n8k8.row.col.f32.tf32.tf32.f32 "
        "{%0,%1,%2,%3}, {%4,%5,%6,%7}, {%8,%9}, {%0,%1,%2,%3};\n"
        : "+f"(c[0]), "+f"(c[1]), "+f"(c[2]), "+f"(c[3])
        : "r"(a[0]), "r"(a[1]), "r"(a[2]), "r"(a[3]), "r"(b[0]), "r"(b[1]));
}

#define CP_ASYNC16(saddr, gptr) \
    asm volatile("cp.async.cg.shared.global [%0], [%1], 16;\n" \
                 :: "r"(saddr), "l"(gptr))
#define CP_COMMIT() asm volatile("cp.async.commit_group;\n" ::: "memory")

template <int N>
__device__ __forceinline__ void cp_wait_group() {
    asm volatile("cp.async.wait_group %0;\n" :: "n"(N) : "memory");
}

// Fragment index functions (float units).
// A operand [M][K], 16x8 blocks of 128 floats. Lane L holds a0..a3 contiguous.
//   a0=(r,c) r<8,c<4; a1=(r+8,c); a2=(r,c+4); a3=(r+8,c+4); L=(r%8)*4+(c%4)
__device__ __forceinline__ size_t fragA_idx(int r, int c, int K) {
    size_t blk = (size_t)(r >> 4) * (K >> 3) + (c >> 3);
    int L = ((r & 7) << 2) + (c & 3);
    int j = (((c >> 2) & 1) << 1) + ((r >> 3) & 1);
    return blk * 128 + (size_t)(L * 4 + j);
}
// B operand [N][K], 8x8 blocks of 64 floats. Lane L holds b0,b1 contiguous.
//   b0: k=lid%4, n=lid/4; b1: k+4. L=(n%8)*4+(k%4)
__device__ __forceinline__ size_t fragB_idx(int n, int k, int K) {
    size_t blk = (size_t)(n >> 3) * (K >> 3) + (k >> 3);
    int L = ((n & 7) << 2) + (k & 3);
    int j = (k >> 2) & 1;
    return blk * 64 + (size_t)(L * 2 + j);
}

// ---------------------------------------------------------------------------
// Merged prep kernel: tf32-round + fragment reorder for all four operands.
//   [0,2048):     ctx   -> g_ctx_f (A-frag, K=512)
//   [2048,2176):  W^T   -> g_Wt_f  (B-frag, K=512)
//   [2176,3200):  V     -> g_V_f   (B-frag, K=256)
//   [3200,4224):  U^T   -> g_Ut_f  (B-frag, K=4096)
// ---------------------------------------------------------------------------
__global__ __launch_bounds__(256)
void prep_all(const float* __restrict__ ctx, const float* __restrict__ W,
              const float* __restrict__ V, const float* __restrict__ U)
{
    __shared__ float tile[32][33];
    int b = blockIdx.x, tid = threadIdx.x;
    if (b < 2048) {
        size_t i = ((size_t)b * 256 + tid) * 4;
        int r = (int)(i / N_CTX), c = (int)(i % N_CTX);
        float4 v = *(const float4*)(ctx + i);
        g_ctx_f[fragA_idx(r, c + 0, N_CTX)] = to_tf32f(v.x);
        g_ctx_f[fragA_idx(r, c + 1, N_CTX)] = to_tf32f(v.y);
        g_ctx_f[fragA_idx(r, c + 2, N_CTX)] = to_tf32f(v.z);
        g_ctx_f[fragA_idx(r, c + 3, N_CTX)] = to_tf32f(v.w);
    } else if (b < 2176) {
        int bb = b - 2048;                 // W: R=512 rows(k), C=256 cols(n)
        int c0 = (bb & 7) * 32;
        int r0 = (bb >> 3) * 32;
        int tx = tid & 31, ty = tid >> 5;
        for (int i = ty; i < 32; i += 8)
            tile[i][tx] = W[(size_t)(r0 + i) * RANK + c0 + tx];
        __syncthreads();
        for (int i = ty; i < 32; i += 8) {
            int n = c0 + i, k = r0 + tx;
            g_Wt_f[fragB_idx(n, k, N_CTX)] = to_tf32f(tile[tx][i]);
        }
    } else if (b < 3200) {
        int bb = b - 2176;                 // V: [N=4096][K=256]
        size_t i = ((size_t)bb * 256 + tid) * 4;
        int n = (int)(i / RANK), k = (int)(i % RANK);
        float4 v = *(const float4*)(V + i);
        g_V_f[fragB_idx(n, k + 0, RANK)] = to_tf32f(v.x);
        g_V_f[fragB_idx(n, k + 1, RANK)] = to_tf32f(v.y);
        g_V_f[fragB_idx(n, k + 2, RANK)] = to_tf32f(v.z);
        g_V_f[fragB_idx(n, k + 3, RANK)] = to_tf32f(v.w);
    } else {
        int bb = b - 3200;                 // U: R=4096 rows(k), C=256 cols(n)
        int c0 = (bb & 7) * 32;
        int r0 = (bb >> 3) * 32;
        int tx = tid & 31, ty = tid >> 5;
        for (int i = ty; i < 32; i += 8)
            tile[i][tx] = U[(size_t)(r0 + i) * RANK + c0 + tx];
        __syncthreads();
        for (int i = ty; i < 32; i += 8) {
            int n = c0 + i, k = r0 + tx;
            g_Ut_f[fragB_idx(n, k, N_IN)] = to_tf32f(tile[tx][i]);
        }
    }
}

// ---------------------------------------------------------------------------
// Template GEMM, tf32 single-pass, fragment-ordered operands.
//   EPI 0: chi -> g_schi (A-frag order)   EPI 2: out = relu(acc + 2*bias)
// ---------------------------------------------------------------------------
template <int TILEM, int TILEN, int WARPS_M, int WARPS_N, int KTOT, int EPI,
          int STAGES, int MINCTA>
__global__ __launch_bounds__(WARPS_M * WARPS_N * 32, MINCTA)
void mma_gemm(float* __restrict__ outp,
              const float* __restrict__ ev0,   // EPI0: S, EPI2: bias
              const float* __restrict__ ev1)   // EPI0: Bvec
{
    constexpr int THREADS = WARPS_M * WARPS_N * 32;
    constexpr int WM = TILEM / WARPS_M;
    constexpr int MI = WM / 16;
    constexpr int NI = 4;                    // 32 n per warp
    constexpr int ASTG = TILEM * 128;        // bytes per A stage (TILEM x 32 fp32)
    constexpr int BSTGB = TILEN * 128;
    constexpr int STG = ASTG + BSTGB;
    constexpr int NC  = KTOT / 32;
    constexpr int A_IT = TILEM * 8 / THREADS;
    constexpr int B_IT = TILEN * 8 / THREADS;
    static_assert(WARPS_N * 32 == TILEN, "tile mismatch");

    extern __shared__ char smem[];
    const uint32_t sb = smem_to_u32(smem);

    const int tid = threadIdx.x;
    const int wid = tid >> 5, lid = tid & 31;
    const int wm = wid / WARPS_N, wn = wid % WARPS_N;
    const int warp_row = wm * WM;
    const int warp_col = wn * 32;
    const int brow = blockIdx.y * TILEM;
    const int bn0  = blockIdx.x * TILEN;

    const float* Ag = (EPI == 0) ? g_ctx_f : g_t_f;
    const float* Bg = (EPI == 0) ? g_Wt_f : g_V_f;
    const int KB = KTOT >> 3;
    const int abm = brow >> 4;
    const int bbn = bn0 >> 3;

    float acc[MI][NI][4];
#pragma unroll
    for (int mi = 0; mi < MI; mi++)
#pragma unroll
        for (int ni = 0; ni < NI; ni++)
#pragma unroll
            for (int q = 0; q < 4; q++) acc[mi][ni][q] = 0.f;

    auto load_stage = [&](int s, int k0) {
        const uint32_t st = sb + (uint32_t)(s * STG);
        const int bk = k0 >> 3;
#pragma unroll
        for (int it = 0; it < A_IT; it++) {
            int flat = it * THREADS + tid;
            int blkl = flat >> 5, within = (flat & 31) * 16;
            int mi = blkl >> 2, ks = blkl & 3;
            size_t gb = ((size_t)(abm + mi) * KB + bk + ks) * 512 + within;
            CP_ASYNC16(st + (uint32_t)(blkl * 512 + within), (const char*)Ag + gb);
        }
#pragma unroll
        for (int it = 0; it < B_IT; it++) {
            int flat = it * THREADS + tid;
            int blkl = flat >> 4, within = (flat & 15) * 16;
            int bn = blkl >> 2, ks = blkl & 3;
            size_t gb = ((size_t)(bbn + bn) * KB + bk + ks) * 256 + within;
            CP_ASYNC16(st + (uint32_t)(ASTG + blkl * 256 + within), (const char*)Bg + gb);
        }
    };

#pragma unroll
    for (int s = 0; s < STAGES - 1; s++) {
        load_stage(s, s * 32);
        CP_COMMIT();
    }

    for (int ch = 0; ch < NC; ch++) {
        cp_wait_group<STAGES - 2>();
        __syncthreads();

        if (ch + STAGES - 1 < NC)
            load_stage((ch + STAGES - 1) % STAGES, (ch + STAGES - 1) * 32);
        CP_COMMIT();

        const uint32_t cb = sb + (uint32_t)((ch % STAGES) * STG);
        const uint32_t Ab = cb, Bb = cb + ASTG;
#pragma unroll
        for (int ks = 0; ks < 4; ks++) {
            uint32_t af[MI][4], bf[NI][2];
#pragma unroll
            for (int mi = 0; mi < MI; mi++)
                lds128(af[mi], Ab + (uint32_t)(((((warp_row >> 4) + mi) << 2) + ks) * 512 + lid * 16));
#pragma unroll
            for (int ni = 0; ni < NI; ni++)
                lds64(bf[ni], Bb + (uint32_t)(((((warp_col >> 3) + ni) << 2) + ks) * 256 + lid * 8));
#pragma unroll
            for (int mi = 0; mi < MI; mi++)
#pragma unroll
                for (int ni = 0; ni < NI; ni++)
                    mma_tf32(acc[mi][ni], af[mi], bf[ni]);
        }
    }

    const int g = lid >> 2, t = lid & 3;
#pragma unroll
    for (int mi = 0; mi < MI; mi++) {
#pragma unroll
        for (int ni = 0; ni < NI; ni++) {
            int row0 = brow + warp_row + mi * 16 + g;
            int row1 = row0 + 8;
            int col  = bn0 + warp_col + ni * 8 + 2 * t;
            const float* a = acc[mi][ni];
            if (EPI == 0) {
                float bv0 = ev1[col], bv1 = ev1[col + 1];
                float s0 = ev0[col], s1 = ev0[col + 1];
                g_schi[fragA_idx(row0, col,     RANK)] = s0 / (1.f + expf(-(a[0] + bv0)));
                g_schi[fragA_idx(row0, col + 1, RANK)] = s1 / (1.f + expf(-(a[1] + bv1)));
                g_schi[fragA_idx(row1, col,     RANK)] = s0 / (1.f + expf(-(a[2] + bv0)));
                g_schi[fragA_idx(row1, col + 1, RANK)] = s1 / (1.f + expf(-(a[3] + bv1)));
            } else {
                float b0 = 2.f * ev0[col], b1 = 2.f * ev0[col + 1];
                float2 r0 = make_float2(fmaxf(a[0] + b0, 0.f), fmaxf(a[1] + b1, 0.f));
                float2 r1 = make_float2(fmaxf(a[2] + b0, 0.f), fmaxf(a[3] + b1, 0.f));
                *(float2*)(outp + (size_t)row0 * UNITS + col) = r0;
                *(float2*)(outp + (size_t)row1 * UNITS + col) = r1;
            }
        }
    }
}

// ---------------------------------------------------------------------------
// GEMM1 fused tf32: 64x128 tile, 128 threads (1x4 warps), MI=4, K-split x2.
//   A: LDG fp32 -> cvt.rna.tf32 -> STS fragment layout (2 smem stages)
//   B: 4-stage cp.async of g_Ut_f fragments.
// ---------------------------------------------------------------------------
__global__ __launch_bounds__(128, 2)
void gemm1_fused(const float* __restrict__ Afp)
{
    constexpr int KTOT = N_IN;
    constexpr int KSEG = KTOT / 2;       // 2048
    constexpr int NC = KSEG / 32;        // 64
    constexpr int ASTG = 64 * 128;       // 8192 B per A stage
    constexpr int BSTGB = 128 * 128;     // 16384 B per B stage
    constexpr int BSTAGES = 4;
    constexpr int KB = KTOT >> 3;        // 512
    // smem: A 2*8192 = 16384 ; B 4*16384 = 65536 ; total 81920 -> 2 CTAs/SM

    extern __shared__ char smem[];
    const uint32_t sb = smem_to_u32(smem);
    const uint32_t sbB = sb + 2 * ASTG;

    const int tid = threadIdx.x;
    const int wid = tid >> 5, lid = tid & 31;
    const int warp_col = wid * 32;
    const int brow = blockIdx.y * 64;
    const int bn0  = blockIdx.x * 128;
    const int kseg = blockIdx.z;
    const int koff = kseg * KSEG;

    float acc[4][4][4];
#pragma unroll
    for (int mi = 0; mi < 4; mi++)
#pragma unroll
        for (int ni = 0; ni < 4; ni++)
#pragma unroll
            for (int q = 0; q < 4; q++) acc[mi][ni][q] = 0.f;

    auto ldgA = [&](int k0, float4* pf) {
#pragma unroll
        for (int it = 0; it < 4; it++) {
            int flat = it * 128 + tid;
            int row = flat >> 3, seg = flat & 7;
            pf[it] = *(const float4*)(Afp + (size_t)(brow + row) * KTOT + k0 + seg * 4);
        }
    };
    // write fragment-ordered tf32 into A stage s
    auto cvtA = [&](int s, const float4* pf) {
        float* base = (float*)(smem + s * ASTG);
#pragma unroll
        for (int it = 0; it < 4; it++) {
            int flat = it * 128 + tid;
            int row = flat >> 3, c0 = (flat & 7) * 4;
            float v[4] = {pf[it].x, pf[it].y, pf[it].z, pf[it].w};
#pragma unroll
            for (int q = 0; q < 4; q++) {
                int c = c0 + q;
                int idx = (((row >> 4) << 2) + (c >> 3)) * 128 +
                          (((row & 7) << 2) + (c & 3)) * 4 +
                          ((((c >> 2) & 1) << 1) + ((row >> 3) & 1));
                base[idx] = to_tf32f(v[q]);
            }
        }
    };
    auto loadB = [&](int s, int k0) {
        uint32_t st = sbB + (uint32_t)(s * BSTGB);
        const int bk = k0 >> 3;
#pragma unroll
        for (int it = 0; it < 8; it++) {
            int flat = it * 128 + tid;
            int blkl = flat >> 4, within = (flat & 15) * 16;
            int bn = blkl >> 2, ks = blkl & 3;
            size_t gb = ((size_t)((bn0 >> 3) + bn) * KB + bk + ks) * 256 + within;
            CP_ASYNC16(st + (uint32_t)(blkl * 256 + within), (const char*)g_Ut_f + gb);
        }
    };

    // prologue
    float4 pf_cur[4], pf_nxt[4];
    ldgA(koff, pf_cur);
    cvtA(0, pf_cur);
    ldgA(koff + 32, pf_cur);
#pragma unroll
    for (int s = 0; s < BSTAGES - 1; s++) {
        loadB(s, koff + s * 32);
        CP_COMMIT();
    }

    for (int ch = 0; ch < NC; ch++) {
        cp_wait_group<BSTAGES - 2>();
        __syncthreads();

        if (ch + 2 < NC) ldgA(koff + (ch + 2) * 32, pf_nxt);
        if (ch + 1 < NC) cvtA((ch + 1) & 1, pf_cur);
        if (ch + BSTAGES - 1 < NC)
            loadB((ch + BSTAGES - 1) % BSTAGES, koff + (ch + BSTAGES - 1) * 32);
        CP_COMMIT();

        const uint32_t Ab = sb + (uint32_t)((ch & 1) * ASTG);
        const uint32_t Bb = sbB + (uint32_t)((ch % BSTAGES) * BSTGB);
#pragma unroll
        for (int ks = 0; ks < 4; ks++) {
            uint32_t af[4][4], bf[4][2];
#pragma unroll
            for (int mi = 0; mi < 4; mi++)
                lds128(af[mi], Ab + (uint32_t)(((mi << 2) + ks) * 512 + lid * 16));
#pragma unroll
            for (int ni = 0; ni < 4; ni++)
                lds64(bf[ni], Bb + (uint32_t)(((((warp_col >> 3) + ni) << 2) + ks) * 256 + lid * 8));
#pragma unroll
            for (int mi = 0; mi < 4; mi++)
#pragma unroll
                for (int ni = 0; ni < 4; ni++)
                    mma_tf32(acc[mi][ni], af[mi], bf[ni]);
        }
#pragma unroll
        for (int q = 0; q < 4; q++) pf_cur[q] = pf_nxt[q];
    }

    // epilogue: fp32 partial -> g_part[kseg] (A-frag order)
    float* dst = &g_part[kseg][0];
    const int g = lid >> 2, t = lid & 3;
#pragma unroll
    for (int mi = 0; mi < 4; mi++) {
#pragma unroll
        for (int ni = 0; ni < 4; ni++) {
            int row0 = brow + mi * 16 + g;
            int row1 = row0 + 8;
            int col  = bn0 + warp_col + ni * 8 + 2 * t;
            const float* a = acc[mi][ni];
            dst[fragA_idx(row0, col,     RANK)] = a[0];
            dst[fragA_idx(row0, col + 1, RANK)] = a[1];
            dst[fragA_idx(row1, col,     RANK)] = a[2];
            dst[fragA_idx(row1, col + 1, RANK)] = a[3];
        }
    }
}

// ---------------------------------------------------------------------------
// k_finish: t = tf32round((p0 + p1) * schi) -> g_t_f (all arrays elementwise
// aligned in A-frag order, so this is a pure linear pass).
// ---------------------------------------------------------------------------
__global__ __launch_bounds__(256)
void k_finish()
{
    size_t i = ((size_t)blockIdx.x * 256 + threadIdx.x) * 4;
    float4 p0 = *(const float4*)(&g_part[0][i]);
    float4 p1 = *(const float4*)(&g_part[1][i]);
    float4 sc = *(const float4*)(g_schi + i);
    float4 t;
    t.x = to_tf32f((p0.x + p1.x) * sc.x);
    t.y = to_tf32f((p0.y + p1.y) * sc.y);
    t.z = to_tf32f((p0.z + p1.z) * sc.z);
    t.w = to_tf32f((p0.w + p1.w) * sc.w);
    *(float4*)(g_t_f + i) = t;
}

// ---------------------------------------------------------------------------
// Launch.
// ---------------------------------------------------------------------------
extern "C" void kernel_launch(void* const* d_in, const int* in_sizes, int n_in,
                              void* d_out, int out_size)
{
    const float* inputs  = (const float*)d_in[0];
    const float* context = (const float*)d_in[1];
    const float* U       = (const float*)d_in[2];
    const float* S       = (const float*)d_in[3];
    const float* V       = (const float*)d_in[4];
    const float* W       = (const float*)d_in[5];
    const float* Bvec    = (const float*)d_in[6];
    const float* bias    = (const float*)d_in[7];
    float* out = (float*)d_out;

    const int smem_chi = 4 * (128 * 128 + 64 * 128);   // 98304
    const int smem_g1  = 2 * 8192 + 4 * 16384;         // 81920 -> 2 CTAs/SM
    const int smem_g2  = 2 * (128 * 128 + 128 * 128);  // 65536 -> 2 CTAs/SM

    cudaFuncSetAttribute(mma_gemm<128, 64, 4, 2, 512, 0, 4, 1>,
                         cudaFuncAttributeMaxDynamicSharedMemorySize, smem_chi);
    cudaFuncSetAttribute(gemm1_fused,
                         cudaFuncAttributeMaxDynamicSharedMemorySize, smem_g1);
    cudaFuncSetAttribute(mma_gemm<128, 128, 2, 4, 256, 2, 2, 2>,
                         cudaFuncAttributeMaxDynamicSharedMemorySize, smem_g2);

    // launch 0: all conversions (tf32 round + fragment reorder)
    prep_all<<<4224, 256>>>(context, W, V, U);
    // launch 1: chi = S*sigmoid(context @ W^T + B)  [4096 x 256], K=512
    mma_gemm<128, 64, 4, 2, 512, 0, 4, 1><<<dim3(RANK / 64, B_SZ / 128), 256, smem_chi>>>(
        nullptr, S, Bvec);
    // launch 2: gemm1 (K-split x2): partials of inputs @ U^T
    gemm1_fused<<<dim3(RANK / 128, B_SZ / 64, 2), 128, smem_g1>>>(inputs);
    // launch 3: finish (reduce partials, scale by schi, tf32 round)
    k_finish<<<(B_SZ * RANK) / 1024, 256>>>();
    // launch 4: out = relu(t @ V^T + 2*bias)  [4096 x 4096], K=256
    mma_gemm<128, 128, 2, 4, 256, 2, 2, 2><<<dim3(UNITS / 128, B_SZ / 128), 256, smem_g2>>>(
        out, bias, nullptr);
}